// round 7
// baseline (speedup 1.0000x reference)
#include <cuda_runtime.h>
#include <math.h>

#define D_MODEL 1024
#define SEQ     4096
#define NHEAD   16
#define DK      64

// Scratch (allocation-free: __device__ globals)
__device__ float g_Q[SEQ * D_MODEL];
__device__ float g_K[SEQ * D_MODEL];
__device__ float g_V[SEQ * D_MODEL];
__device__ float g_O[SEQ * D_MODEL];

// ============================================================================
// GEMM: C[M,1024] = A[M,1024] @ W[1024,1024]^T + bias   (torch Linear)
// A row-major, W row-major [out,in] -> both operands contiguous along K (NT).
// 128x128 tile, BK=8, 256 threads, 8x8 register micro-tile (split 4+4),
// register prefetch of the next K-slab to hide LDG latency.
// ============================================================================
__global__ __launch_bounds__(256, 2)
void gemm_bias_nt(const float* __restrict__ A, const float* __restrict__ W,
                  const float* __restrict__ bias, float* __restrict__ C) {
    __shared__ float As[8][128];   // As[k][m]
    __shared__ float Bs[8][128];   // Bs[k][n]

    const int tid = threadIdx.x;
    const int tx  = tid & 15;      // 0..15 -> cols
    const int ty  = tid >> 4;      // 0..15 -> rows
    const int bm  = blockIdx.y * 128;
    const int bn  = blockIdx.x * 128;

    // cooperative load mapping: 128 rows x 8 k, one float4 per thread
    const int lrow = tid >> 1;          // 0..127
    const int lcol = (tid & 1) * 4;     // 0 or 4
    const float* Ap = A + (bm + lrow) * D_MODEL + lcol;
    const float* Wp = W + (bn + lrow) * D_MODEL + lcol;

    float acc[8][8];
#pragma unroll
    for (int i = 0; i < 8; i++)
#pragma unroll
        for (int j = 0; j < 8; j++) acc[i][j] = 0.0f;

    // prefetch first slab
    float4 av = *(const float4*)Ap;
    float4 wv = *(const float4*)Wp;

    for (int k0 = 0; k0 < D_MODEL; k0 += 8) {
        __syncthreads();
        As[lcol + 0][lrow] = av.x; As[lcol + 1][lrow] = av.y;
        As[lcol + 2][lrow] = av.z; As[lcol + 3][lrow] = av.w;
        Bs[lcol + 0][lrow] = wv.x; Bs[lcol + 1][lrow] = wv.y;
        Bs[lcol + 2][lrow] = wv.z; Bs[lcol + 3][lrow] = wv.w;
        __syncthreads();

        if (k0 + 8 < D_MODEL) {   // prefetch next slab (hidden under compute)
            av = *(const float4*)(Ap + k0 + 8);
            wv = *(const float4*)(Wp + k0 + 8);
        }

#pragma unroll
        for (int k = 0; k < 8; k++) {
            float a[8], b[8];
            *(float4*)&a[0] = *(const float4*)&As[k][ty * 4];
            *(float4*)&a[4] = *(const float4*)&As[k][64 + ty * 4];
            *(float4*)&b[0] = *(const float4*)&Bs[k][tx * 4];
            *(float4*)&b[4] = *(const float4*)&Bs[k][64 + tx * 4];
#pragma unroll
            for (int i = 0; i < 8; i++)
#pragma unroll
                for (int j = 0; j < 8; j++)
                    acc[i][j] = fmaf(a[i], b[j], acc[i][j]);
        }
    }

    // epilogue: + bias, coalesced float4 stores
#pragma unroll
    for (int i = 0; i < 8; i++) {
        const int row = bm + ((i < 4) ? (ty * 4 + i) : (64 + ty * 4 + (i - 4)));
        float* Cp = C + row * D_MODEL + bn;
#pragma unroll
        for (int jh = 0; jh < 2; jh++) {
            const int cb = jh * 64 + tx * 4;
            const float4 bv = *(const float4*)(bias + bn + cb);
            float4 o;
            o.x = acc[i][jh * 4 + 0] + bv.x;
            o.y = acc[i][jh * 4 + 1] + bv.y;
            o.z = acc[i][jh * 4 + 2] + bv.z;
            o.w = acc[i][jh * 4 + 3] + bv.w;
            *(float4*)(Cp + cb) = o;
        }
    }
}

// ============================================================================
// Flash attention (fp32, non-causal). One CTA = (head, 64-query block).
// Q,K stored d-major (transposed) in smem so the QK inner loop is
// 2 conflict-free LDS.128 per 16 FFMA. P written float4 row-major, PV reads
// conflict-free. Online softmax with per-row (m,l), row stats reduced via
// shfl.xor across the 16 column-lanes.
// ============================================================================
#define SQ 68   // padded smem stride (multiple of 4 for aligned float4)

__global__ __launch_bounds__(256, 3)
void attn_kernel(const float* __restrict__ Qb, const float* __restrict__ Kb,
                 const float* __restrict__ Vb, float* __restrict__ Ob) {
    extern __shared__ float sm[];
    float* Qts = sm;                 // [64][SQ]  Qts[d*SQ + r]
    float* Kts = Qts + 64 * SQ;      // [64][SQ]  Kts[d*SQ + c]
    float* Ps  = Kts + 64 * SQ;      // [64][SQ]  Ps[r*SQ + k]
    float* Vs  = Ps  + 64 * SQ;      // [64][64]  Vs[k*64 + d]

    const int tid = threadIdx.x;
    const int tx  = tid & 15;        // column group (keys / d-dims)
    const int ty  = tid >> 4;        // row group (queries)
    const int h   = blockIdx.y;
    const int q0  = blockIdx.x * 64;
    const int c0  = h * DK;

    // Load Q tile transposed + pre-scaled by 1/sqrt(dk)
#pragma unroll
    for (int p = 0; p < 4; p++) {
        const int lin = p * 1024 + tid * 4;
        const int r  = lin >> 6;
        const int d0 = lin & 63;
        const float4 v = *(const float4*)&Qb[(q0 + r) * D_MODEL + c0 + d0];
        Qts[(d0 + 0) * SQ + r] = v.x * 0.125f;
        Qts[(d0 + 1) * SQ + r] = v.y * 0.125f;
        Qts[(d0 + 2) * SQ + r] = v.z * 0.125f;
        Qts[(d0 + 3) * SQ + r] = v.w * 0.125f;
    }

    float mrun[4], lrun[4], o[4][4];
#pragma unroll
    for (int r = 0; r < 4; r++) {
        mrun[r] = -1e30f;
        lrun[r] = 0.0f;
#pragma unroll
        for (int c = 0; c < 4; c++) o[r][c] = 0.0f;
    }

    for (int kb = 0; kb < SEQ / 64; kb++) {
        const int k0 = kb * 64;
        __syncthreads();   // previous iteration's readers of Kts/Vs/Ps done (also orders Qts on kb=0)

        // Load K (transposed) and V (direct), coalesced float4 global reads
#pragma unroll
        for (int p = 0; p < 4; p++) {
            const int lin = p * 1024 + tid * 4;
            const int c  = lin >> 6;
            const int d0 = lin & 63;
            const float4 kv = *(const float4*)&Kb[(k0 + c) * D_MODEL + c0 + d0];
            Kts[(d0 + 0) * SQ + c] = kv.x;
            Kts[(d0 + 1) * SQ + c] = kv.y;
            Kts[(d0 + 2) * SQ + c] = kv.z;
            Kts[(d0 + 3) * SQ + c] = kv.w;
            const float4 vv = *(const float4*)&Vb[(k0 + c) * D_MODEL + c0 + d0];
            *(float4*)&Vs[c * 64 + d0] = vv;
        }
        __syncthreads();

        // ---- S = (Q*scale) @ K^T  (4x4 per thread) ----
        float s[4][4];
#pragma unroll
        for (int r = 0; r < 4; r++)
#pragma unroll
            for (int c = 0; c < 4; c++) s[r][c] = 0.0f;

#pragma unroll 8
        for (int d = 0; d < 64; d++) {
            float a[4], b[4];
            *(float4*)a = *(const float4*)&Qts[d * SQ + ty * 4];
            *(float4*)b = *(const float4*)&Kts[d * SQ + tx * 4];
#pragma unroll
            for (int r = 0; r < 4; r++)
#pragma unroll
                for (int c = 0; c < 4; c++)
                    s[r][c] = fmaf(a[r], b[c], s[r][c]);
        }

        // ---- online softmax update + stage P into smem ----
#pragma unroll
        for (int r = 0; r < 4; r++) {
            float mr = fmaxf(fmaxf(s[r][0], s[r][1]), fmaxf(s[r][2], s[r][3]));
            mr = fmaxf(mr, __shfl_xor_sync(0xffffffffu, mr, 1));
            mr = fmaxf(mr, __shfl_xor_sync(0xffffffffu, mr, 2));
            mr = fmaxf(mr, __shfl_xor_sync(0xffffffffu, mr, 4));
            mr = fmaxf(mr, __shfl_xor_sync(0xffffffffu, mr, 8));
            const float mnew  = fmaxf(mrun[r], mr);
            const float alpha = __expf(mrun[r] - mnew);
            mrun[r] = mnew;

            float4 pv;
            pv.x = __expf(s[r][0] - mnew);
            pv.y = __expf(s[r][1] - mnew);
            pv.z = __expf(s[r][2] - mnew);
            pv.w = __expf(s[r][3] - mnew);
            float rs = pv.x + pv.y + pv.z + pv.w;
            rs += __shfl_xor_sync(0xffffffffu, rs, 1);
            rs += __shfl_xor_sync(0xffffffffu, rs, 2);
            rs += __shfl_xor_sync(0xffffffffu, rs, 4);
            rs += __shfl_xor_sync(0xffffffffu, rs, 8);
            lrun[r] = lrun[r] * alpha + rs;

#pragma unroll
            for (int c = 0; c < 4; c++) o[r][c] *= alpha;

            *(float4*)&Ps[(ty * 4 + r) * SQ + tx * 4] = pv;
        }
        __syncthreads();

        // ---- O += P @ V  (4x4 per thread, contraction over 64 keys) ----
#pragma unroll 4
        for (int k4 = 0; k4 < 16; k4++) {
            float a[4][4];   // a[r][i] = P[4ty+r][4k4+i]
            float v[4][4];   // v[i][c] = V[4k4+i][4tx+c]
#pragma unroll
            for (int r = 0; r < 4; r++)
                *(float4*)a[r] = *(const float4*)&Ps[(ty * 4 + r) * SQ + k4 * 4];
#pragma unroll
            for (int i = 0; i < 4; i++)
                *(float4*)v[i] = *(const float4*)&Vs[(k4 * 4 + i) * 64 + tx * 4];
#pragma unroll
            for (int r = 0; r < 4; r++)
#pragma unroll
                for (int c = 0; c < 4; c++) {
                    float acc = o[r][c];
#pragma unroll
                    for (int i = 0; i < 4; i++)
                        acc = fmaf(a[r][i], v[i][c], acc);
                    o[r][c] = acc;
                }
        }
    }

    // epilogue: O /= l, write to concat-head layout [S, D_MODEL]
#pragma unroll
    for (int r = 0; r < 4; r++) {
        const float inv = 1.0f / lrun[r];
        float4 out;
        out.x = o[r][0] * inv;
        out.y = o[r][1] * inv;
        out.z = o[r][2] * inv;
        out.w = o[r][3] * inv;
        *(float4*)&Ob[(q0 + ty * 4 + r) * D_MODEL + c0 + tx * 4] = out;
    }
}

// ============================================================================
// Launch
// ============================================================================
extern "C" void kernel_launch(void* const* d_in, const int* in_sizes, int n_in,
                              void* d_out, int out_size) {
    (void)in_sizes; (void)n_in; (void)out_size;
    const float* query = (const float*)d_in[0];
    const float* key   = (const float*)d_in[1];
    const float* value = (const float*)d_in[2];
    const float* Wq = (const float*)d_in[3];
    const float* bq = (const float*)d_in[4];
    const float* Wk = (const float*)d_in[5];
    const float* bk = (const float*)d_in[6];
    const float* Wv = (const float*)d_in[7];
    const float* bv = (const float*)d_in[8];
    const float* Wo = (const float*)d_in[9];
    const float* bo = (const float*)d_in[10];
    float* out = (float*)d_out;

    float *pQ, *pK, *pV, *pO;
    cudaGetSymbolAddress((void**)&pQ, g_Q);
    cudaGetSymbolAddress((void**)&pK, g_K);
    cudaGetSymbolAddress((void**)&pV, g_V);
    cudaGetSymbolAddress((void**)&pO, g_O);

    const int ATTN_SMEM = (3 * 64 * SQ + 64 * 64) * (int)sizeof(float);  // 68608 B
    cudaFuncSetAttribute(attn_kernel, cudaFuncAttributeMaxDynamicSharedMemorySize,
                         ATTN_SMEM);

    dim3 gg(D_MODEL / 128, SEQ / 128);   // (8, 32)
    gemm_bias_nt<<<gg, 256>>>(query, Wq, bq, pQ);
    gemm_bias_nt<<<gg, 256>>>(key,   Wk, bk, pK);
    gemm_bias_nt<<<gg, 256>>>(value, Wv, bv, pV);

    dim3 ga(SEQ / 64, NHEAD);            // (64, 16)
    attn_kernel<<<ga, 256, ATTN_SMEM>>>(pQ, pK, pV, pO);

    gemm_bias_nt<<<gg, 256>>>(pO, Wo, bo, out);
}

// round 8
// speedup vs baseline: 1.0005x; 1.0005x over previous
#include <cuda_runtime.h>
#include <math.h>

#define D_MODEL 1024
#define SEQ     4096
#define NHEAD   16
#define DK      64

// Scratch (allocation-free: __device__ globals)
__device__ float g_Q[SEQ * D_MODEL];
__device__ float g_K[SEQ * D_MODEL];
__device__ float g_V[SEQ * D_MODEL];
__device__ float g_O[SEQ * D_MODEL];

// ============================================================================
// GEMM: C[M,1024] = A[M,1024] @ W[1024,1024]^T + bias   (torch Linear)
// A row-major, W row-major [out,in] -> both operands contiguous along K (NT).
// 128x128 tile, BK=8, 256 threads, 8x8 register micro-tile (split 4+4),
// register prefetch of the next K-slab to hide LDG latency.
// ============================================================================
__global__ __launch_bounds__(256, 2)
void gemm_bias_nt(const float* __restrict__ A, const float* __restrict__ W,
                  const float* __restrict__ bias, float* __restrict__ C) {
    __shared__ float As[8][128];   // As[k][m]
    __shared__ float Bs[8][128];   // Bs[k][n]

    const int tid = threadIdx.x;
    const int tx  = tid & 15;      // 0..15 -> cols
    const int ty  = tid >> 4;      // 0..15 -> rows
    const int bm  = blockIdx.y * 128;
    const int bn  = blockIdx.x * 128;

    // cooperative load mapping: 128 rows x 8 k, one float4 per thread
    const int lrow = tid >> 1;          // 0..127
    const int lcol = (tid & 1) * 4;     // 0 or 4
    const float* Ap = A + (bm + lrow) * D_MODEL + lcol;
    const float* Wp = W + (bn + lrow) * D_MODEL + lcol;

    float acc[8][8];
#pragma unroll
    for (int i = 0; i < 8; i++)
#pragma unroll
        for (int j = 0; j < 8; j++) acc[i][j] = 0.0f;

    // prefetch first slab
    float4 av = *(const float4*)Ap;
    float4 wv = *(const float4*)Wp;

    for (int k0 = 0; k0 < D_MODEL; k0 += 8) {
        __syncthreads();
        As[lcol + 0][lrow] = av.x; As[lcol + 1][lrow] = av.y;
        As[lcol + 2][lrow] = av.z; As[lcol + 3][lrow] = av.w;
        Bs[lcol + 0][lrow] = wv.x; Bs[lcol + 1][lrow] = wv.y;
        Bs[lcol + 2][lrow] = wv.z; Bs[lcol + 3][lrow] = wv.w;
        __syncthreads();

        if (k0 + 8 < D_MODEL) {   // prefetch next slab (hidden under compute)
            av = *(const float4*)(Ap + k0 + 8);
            wv = *(const float4*)(Wp + k0 + 8);
        }

#pragma unroll
        for (int k = 0; k < 8; k++) {
            float a[8], b[8];
            *(float4*)&a[0] = *(const float4*)&As[k][ty * 4];
            *(float4*)&a[4] = *(const float4*)&As[k][64 + ty * 4];
            *(float4*)&b[0] = *(const float4*)&Bs[k][tx * 4];
            *(float4*)&b[4] = *(const float4*)&Bs[k][64 + tx * 4];
#pragma unroll
            for (int i = 0; i < 8; i++)
#pragma unroll
                for (int j = 0; j < 8; j++)
                    acc[i][j] = fmaf(a[i], b[j], acc[i][j]);
        }
    }

    // epilogue: + bias, coalesced float4 stores
#pragma unroll
    for (int i = 0; i < 8; i++) {
        const int row = bm + ((i < 4) ? (ty * 4 + i) : (64 + ty * 4 + (i - 4)));
        float* Cp = C + row * D_MODEL + bn;
#pragma unroll
        for (int jh = 0; jh < 2; jh++) {
            const int cb = jh * 64 + tx * 4;
            const float4 bv = *(const float4*)(bias + bn + cb);
            float4 o;
            o.x = acc[i][jh * 4 + 0] + bv.x;
            o.y = acc[i][jh * 4 + 1] + bv.y;
            o.z = acc[i][jh * 4 + 2] + bv.z;
            o.w = acc[i][jh * 4 + 3] + bv.w;
            *(float4*)(Cp + cb) = o;
        }
    }
}

// ============================================================================
// Flash attention (fp32, non-causal). One CTA = (head, 64-query block).
// Q,K stored d-major (transposed) in smem so the QK inner loop is
// 2 conflict-free LDS.128 per 16 FFMA. P written float4 row-major, PV reads
// conflict-free. Online softmax with per-row (m,l), row stats reduced via
// shfl.xor across the 16 column-lanes.
// ============================================================================
#define SQ 68   // padded smem stride (multiple of 4 for aligned float4)

__global__ __launch_bounds__(256, 3)
void attn_kernel(const float* __restrict__ Qb, const float* __restrict__ Kb,
                 const float* __restrict__ Vb, float* __restrict__ Ob) {
    extern __shared__ float sm[];
    float* Qts = sm;                 // [64][SQ]  Qts[d*SQ + r]
    float* Kts = Qts + 64 * SQ;      // [64][SQ]  Kts[d*SQ + c]
    float* Ps  = Kts + 64 * SQ;      // [64][SQ]  Ps[r*SQ + k]
    float* Vs  = Ps  + 64 * SQ;      // [64][64]  Vs[k*64 + d]

    const int tid = threadIdx.x;
    const int tx  = tid & 15;        // column group (keys / d-dims)
    const int ty  = tid >> 4;        // row group (queries)
    const int h   = blockIdx.y;
    const int q0  = blockIdx.x * 64;
    const int c0  = h * DK;

    // Load Q tile transposed + pre-scaled by 1/sqrt(dk)
#pragma unroll
    for (int p = 0; p < 4; p++) {
        const int lin = p * 1024 + tid * 4;
        const int r  = lin >> 6;
        const int d0 = lin & 63;
        const float4 v = *(const float4*)&Qb[(q0 + r) * D_MODEL + c0 + d0];
        Qts[(d0 + 0) * SQ + r] = v.x * 0.125f;
        Qts[(d0 + 1) * SQ + r] = v.y * 0.125f;
        Qts[(d0 + 2) * SQ + r] = v.z * 0.125f;
        Qts[(d0 + 3) * SQ + r] = v.w * 0.125f;
    }

    float mrun[4], lrun[4], o[4][4];
#pragma unroll
    for (int r = 0; r < 4; r++) {
        mrun[r] = -1e30f;
        lrun[r] = 0.0f;
#pragma unroll
        for (int c = 0; c < 4; c++) o[r][c] = 0.0f;
    }

    for (int kb = 0; kb < SEQ / 64; kb++) {
        const int k0 = kb * 64;
        __syncthreads();   // previous iteration's readers of Kts/Vs/Ps done (also orders Qts on kb=0)

        // Load K (transposed) and V (direct), coalesced float4 global reads
#pragma unroll
        for (int p = 0; p < 4; p++) {
            const int lin = p * 1024 + tid * 4;
            const int c  = lin >> 6;
            const int d0 = lin & 63;
            const float4 kv = *(const float4*)&Kb[(k0 + c) * D_MODEL + c0 + d0];
            Kts[(d0 + 0) * SQ + c] = kv.x;
            Kts[(d0 + 1) * SQ + c] = kv.y;
            Kts[(d0 + 2) * SQ + c] = kv.z;
            Kts[(d0 + 3) * SQ + c] = kv.w;
            const float4 vv = *(const float4*)&Vb[(k0 + c) * D_MODEL + c0 + d0];
            *(float4*)&Vs[c * 64 + d0] = vv;
        }
        __syncthreads();

        // ---- S = (Q*scale) @ K^T  (4x4 per thread) ----
        float s[4][4];
#pragma unroll
        for (int r = 0; r < 4; r++)
#pragma unroll
            for (int c = 0; c < 4; c++) s[r][c] = 0.0f;

#pragma unroll 8
        for (int d = 0; d < 64; d++) {
            float a[4], b[4];
            *(float4*)a = *(const float4*)&Qts[d * SQ + ty * 4];
            *(float4*)b = *(const float4*)&Kts[d * SQ + tx * 4];
#pragma unroll
            for (int r = 0; r < 4; r++)
#pragma unroll
                for (int c = 0; c < 4; c++)
                    s[r][c] = fmaf(a[r], b[c], s[r][c]);
        }

        // ---- online softmax update + stage P into smem ----
#pragma unroll
        for (int r = 0; r < 4; r++) {
            float mr = fmaxf(fmaxf(s[r][0], s[r][1]), fmaxf(s[r][2], s[r][3]));
            mr = fmaxf(mr, __shfl_xor_sync(0xffffffffu, mr, 1));
            mr = fmaxf(mr, __shfl_xor_sync(0xffffffffu, mr, 2));
            mr = fmaxf(mr, __shfl_xor_sync(0xffffffffu, mr, 4));
            mr = fmaxf(mr, __shfl_xor_sync(0xffffffffu, mr, 8));
            const float mnew  = fmaxf(mrun[r], mr);
            const float alpha = __expf(mrun[r] - mnew);
            mrun[r] = mnew;

            float4 pv;
            pv.x = __expf(s[r][0] - mnew);
            pv.y = __expf(s[r][1] - mnew);
            pv.z = __expf(s[r][2] - mnew);
            pv.w = __expf(s[r][3] - mnew);
            float rs = pv.x + pv.y + pv.z + pv.w;
            rs += __shfl_xor_sync(0xffffffffu, rs, 1);
            rs += __shfl_xor_sync(0xffffffffu, rs, 2);
            rs += __shfl_xor_sync(0xffffffffu, rs, 4);
            rs += __shfl_xor_sync(0xffffffffu, rs, 8);
            lrun[r] = lrun[r] * alpha + rs;

#pragma unroll
            for (int c = 0; c < 4; c++) o[r][c] *= alpha;

            *(float4*)&Ps[(ty * 4 + r) * SQ + tx * 4] = pv;
        }
        __syncthreads();

        // ---- O += P @ V  (4x4 per thread, contraction over 64 keys) ----
#pragma unroll 4
        for (int k4 = 0; k4 < 16; k4++) {
            float a[4][4];   // a[r][i] = P[4ty+r][4k4+i]
            float v[4][4];   // v[i][c] = V[4k4+i][4tx+c]
#pragma unroll
            for (int r = 0; r < 4; r++)
                *(float4*)a[r] = *(const float4*)&Ps[(ty * 4 + r) * SQ + k4 * 4];
#pragma unroll
            for (int i = 0; i < 4; i++)
                *(float4*)v[i] = *(const float4*)&Vs[(k4 * 4 + i) * 64 + tx * 4];
#pragma unroll
            for (int r = 0; r < 4; r++)
#pragma unroll
                for (int c = 0; c < 4; c++) {
                    float acc = o[r][c];
#pragma unroll
                    for (int i = 0; i < 4; i++)
                        acc = fmaf(a[r][i], v[i][c], acc);
                    o[r][c] = acc;
                }
        }
    }

    // epilogue: O /= l, write to concat-head layout [S, D_MODEL]
#pragma unroll
    for (int r = 0; r < 4; r++) {
        const float inv = 1.0f / lrun[r];
        float4 out;
        out.x = o[r][0] * inv;
        out.y = o[r][1] * inv;
        out.z = o[r][2] * inv;
        out.w = o[r][3] * inv;
        *(float4*)&Ob[(q0 + ty * 4 + r) * D_MODEL + c0 + tx * 4] = out;
    }
}

// ============================================================================
// Launch
// ============================================================================
extern "C" void kernel_launch(void* const* d_in, const int* in_sizes, int n_in,
                              void* d_out, int out_size) {
    (void)in_sizes; (void)n_in; (void)out_size;
    const float* query = (const float*)d_in[0];
    const float* key   = (const float*)d_in[1];
    const float* value = (const float*)d_in[2];
    const float* Wq = (const float*)d_in[3];
    const float* bq = (const float*)d_in[4];
    const float* Wk = (const float*)d_in[5];
    const float* bk = (const float*)d_in[6];
    const float* Wv = (const float*)d_in[7];
    const float* bv = (const float*)d_in[8];
    const float* Wo = (const float*)d_in[9];
    const float* bo = (const float*)d_in[10];
    float* out = (float*)d_out;

    float *pQ, *pK, *pV, *pO;
    cudaGetSymbolAddress((void**)&pQ, g_Q);
    cudaGetSymbolAddress((void**)&pK, g_K);
    cudaGetSymbolAddress((void**)&pV, g_V);
    cudaGetSymbolAddress((void**)&pO, g_O);

    const int ATTN_SMEM = (3 * 64 * SQ + 64 * 64) * (int)sizeof(float);  // 68608 B
    cudaFuncSetAttribute(attn_kernel, cudaFuncAttributeMaxDynamicSharedMemorySize,
                         ATTN_SMEM);

    dim3 gg(D_MODEL / 128, SEQ / 128);   // (8, 32)
    gemm_bias_nt<<<gg, 256>>>(query, Wq, bq, pQ);
    gemm_bias_nt<<<gg, 256>>>(key,   Wk, bk, pK);
    gemm_bias_nt<<<gg, 256>>>(value, Wv, bv, pV);

    dim3 ga(SEQ / 64, NHEAD);            // (64, 16)
    attn_kernel<<<ga, 256, ATTN_SMEM>>>(pQ, pK, pV, pO);

    gemm_bias_nt<<<gg, 256>>>(pO, Wo, bo, out);
}

// round 9
// speedup vs baseline: 2.1912x; 2.1901x over previous
#include <cuda_runtime.h>
#include <math.h>

#define D_MODEL 1024
#define SEQ     4096
#define NHEAD   16
#define DK      64

// Scratch (allocation-free: __device__ globals)
__device__ float g_Q[SEQ * D_MODEL];
__device__ float g_K[SEQ * D_MODEL];
__device__ float g_V[SEQ * D_MODEL];
__device__ float g_O[SEQ * D_MODEL];

// ---------------------------------------------------------------------------
// tf32 helpers. cvt.rna (round-to-nearest) is REQUIRED: raw-bit truncation in
// the mma gives a correlated -2^-11 bias per operand -> ~1e-3 systematic error.
// ---------------------------------------------------------------------------
__device__ __forceinline__ unsigned f2tf(float x) {
    unsigned y;
    asm("cvt.rna.tf32.f32 %0, %1;" : "=r"(y) : "f"(x));
    return y;
}

// D += A(16x8) * B(8x8), tf32 in, fp32 accum
__device__ __forceinline__ void mma8(float* d, const unsigned* a, const unsigned* b) {
    asm volatile(
        "mma.sync.aligned.m16n8k8.row.col.f32.tf32.tf32.f32 "
        "{%0,%1,%2,%3}, {%4,%5,%6,%7}, {%8,%9}, {%0,%1,%2,%3};\n"
        : "+f"(d[0]), "+f"(d[1]), "+f"(d[2]), "+f"(d[3])
        : "r"(a[0]), "r"(a[1]), "r"(a[2]), "r"(a[3]), "r"(b[0]), "r"(b[1]));
}

// Permutation within each 8-wide k-block so that the (c, c+4) fragment pair is
// adjacent in smem -> every fragment load is one LDS.64.
// pos(k) = (k & ~7) + (k%4)*2 + (k/4)%2
__device__ __forceinline__ int kperm(int k) {
    return (k & ~7) + ((k & 3) << 1) + ((k >> 2) & 1);
}

// ============================================================================
// GEMM: C[M,1024] = A[M,1024] @ W[1024,1024]^T + bias  (tf32 mma, NT)
// Tile 128x128x16, 8 warps as 2(M)x4(N), warp tile 64x32 (4 m-atoms x 4 n-atoms).
// smem stride 24 words: fragment LDS.64 banks = {24g%32 + 2c + w} -> conflict-free.
// ============================================================================
#define GSTR 24

__global__ __launch_bounds__(256, 2)
void gemm_tf32(const float* __restrict__ A, const float* __restrict__ W,
               const float* __restrict__ bias, float* __restrict__ C) {
    __shared__ unsigned As[128 * GSTR];
    __shared__ unsigned Bs[128 * GSTR];

    const int tid  = threadIdx.x;
    const int lane = tid & 31;
    const int warp = tid >> 5;
    const int g = lane >> 2, c = lane & 3;
    const int wm = (warp >> 2) * 64;      // 0 / 64
    const int wn = (warp & 3) * 32;       // 0,32,64,96
    const int bm = blockIdx.y * 128;
    const int bn = blockIdx.x * 128;

    const int srow = tid >> 1;            // 0..127
    const int sk   = (tid & 1) * 8;       // 0 / 8
    const float* Ap = A + (bm + srow) * D_MODEL + sk;
    const float* Wp = W + (bn + srow) * D_MODEL + sk;

    float acc[4][4][4];
#pragma unroll
    for (int i = 0; i < 4; i++)
#pragma unroll
        for (int j = 0; j < 4; j++)
#pragma unroll
            for (int r = 0; r < 4; r++) acc[i][j][r] = 0.0f;

    // register prefetch of first slab
    float4 av0 = *(const float4*)Ap;
    float4 av1 = *(const float4*)(Ap + 4);
    float4 wv0 = *(const float4*)Wp;
    float4 wv1 = *(const float4*)(Wp + 4);

    for (int k0 = 0; k0 < D_MODEL; k0 += 16) {
        __syncthreads();
        {
            unsigned* ad = As + srow * GSTR + sk;
            unsigned* bd = Bs + srow * GSTR + sk;
            const float aj[8] = {av0.x, av0.y, av0.z, av0.w, av1.x, av1.y, av1.z, av1.w};
            const float wj[8] = {wv0.x, wv0.y, wv0.z, wv0.w, wv1.x, wv1.y, wv1.z, wv1.w};
#pragma unroll
            for (int j = 0; j < 8; j++) {
                const int p = ((j & 3) << 1) + (j >> 2);
                ad[p] = f2tf(aj[j]);
                bd[p] = f2tf(wj[j]);
            }
        }
        __syncthreads();

        if (k0 + 16 < D_MODEL) {          // prefetch next slab under compute
            av0 = *(const float4*)(Ap + k0 + 16);
            av1 = *(const float4*)(Ap + k0 + 20);
            wv0 = *(const float4*)(Wp + k0 + 16);
            wv1 = *(const float4*)(Wp + k0 + 20);
        }

#pragma unroll
        for (int s = 0; s < 2; s++) {     // two k8 steps per slab
            unsigned af[4][4], bf[4][2];
#pragma unroll
            for (int ma = 0; ma < 4; ma++) {
                const uint2 t0 = *(const uint2*)(As + (wm + ma * 16 + g)     * GSTR + s * 8 + c * 2);
                const uint2 t1 = *(const uint2*)(As + (wm + ma * 16 + g + 8) * GSTR + s * 8 + c * 2);
                af[ma][0] = t0.x; af[ma][1] = t1.x; af[ma][2] = t0.y; af[ma][3] = t1.y;
            }
#pragma unroll
            for (int na = 0; na < 4; na++) {
                const uint2 t = *(const uint2*)(Bs + (wn + na * 8 + g) * GSTR + s * 8 + c * 2);
                bf[na][0] = t.x; bf[na][1] = t.y;
            }
#pragma unroll
            for (int ma = 0; ma < 4; ma++)
#pragma unroll
                for (int na = 0; na < 4; na++)
                    mma8(acc[ma][na], af[ma], bf[na]);
        }
    }

    // epilogue: + bias, float2 stores (C layout: row g/g+8, cols 2c,2c+1)
#pragma unroll
    for (int na = 0; na < 4; na++) {
        const int col = bn + wn + na * 8 + 2 * c;
        const float2 bb = *(const float2*)(bias + col);
#pragma unroll
        for (int ma = 0; ma < 4; ma++) {
            const int r0 = bm + wm + ma * 16 + g;
            float2 v0 = {acc[ma][na][0] + bb.x, acc[ma][na][1] + bb.y};
            float2 v1 = {acc[ma][na][2] + bb.x, acc[ma][na][3] + bb.y};
            *(float2*)(C + r0 * D_MODEL + col)       = v0;
            *(float2*)(C + (r0 + 8) * D_MODEL + col) = v1;
        }
    }
}

// ============================================================================
// Flash attention with tf32 mma. One CTA = (head, 256-query block).
// 8 warps, each owns 32 query rows (2 m-atoms) -> softmax is warp-local
// (row reduction = shfl over the lane%4 quad). K/V blocks of 64 keys.
// Qs/Ks/Ps use the kperm layout (LDS.64 fragments, stride 72 conflict-free);
// Vs stored plain: PV B-fragments are scalar LDS with banks 8c+g = 0..31.
// exp via exp2f with log2(e)/8 folded into Q.
// ============================================================================
#define ASTR 72
#define MQ   256

__global__ __launch_bounds__(256, 1)
void attn_tf32(const float* __restrict__ Qb, const float* __restrict__ Kb,
               const float* __restrict__ Vb, float* __restrict__ Ob) {
    extern __shared__ unsigned smA[];
    unsigned* Qs = smA;                 // [MQ][ASTR]  perm(d)
    unsigned* Ps = Qs + MQ * ASTR;      // [MQ][ASTR]  perm(key)
    unsigned* Ks = Ps + MQ * ASTR;      // [64][ASTR]  perm(d)
    unsigned* Vs = Ks + 64 * ASTR;      // [64][ASTR]  plain d

    const int tid = threadIdx.x, lane = tid & 31, warp = tid >> 5;
    const int g = lane >> 2, c = lane & 3;
    const int h = blockIdx.y, q0 = blockIdx.x * MQ, c0 = h * DK;
    const int wq = warp * 32;

    const float QS = 0.125f * 1.4426950408889634f;   // (1/sqrt(dk)) * log2(e)

    // ---- stage Q (scaled, tf32, perm) ----
#pragma unroll
    for (int p = 0; p < (MQ * DK) / (256 * 4); p++) {   // 16 passes
        const int idx = p * 1024 + tid * 4;
        const int r = idx >> 6, d0 = idx & 63;
        const float4 v = *(const float4*)(Qb + (q0 + r) * D_MODEL + c0 + d0);
        unsigned* dst = Qs + r * ASTR;
        const float vv[4] = {v.x, v.y, v.z, v.w};
#pragma unroll
        for (int j = 0; j < 4; j++) dst[kperm(d0 + j)] = f2tf(vv[j] * QS);
    }

    float o[2][8][4];
    float mrun[2][2], lrun[2][2];
#pragma unroll
    for (int ma = 0; ma < 2; ma++) {
        mrun[ma][0] = mrun[ma][1] = -1e30f;
        lrun[ma][0] = lrun[ma][1] = 0.0f;
#pragma unroll
        for (int na = 0; na < 8; na++)
#pragma unroll
            for (int r = 0; r < 4; r++) o[ma][na][r] = 0.0f;
    }

    const int pe = ((2 * c) & 3) * 2 + (((2 * c) >> 2) & 1);          // {0,4,1,5}
    const int po = ((2 * c + 1) & 3) * 2 + (((2 * c + 1) >> 2) & 1);  // {2,6,3,7}

    for (int kb = 0; kb < SEQ / 64; kb++) {
        const int kr = kb * 64;
        __syncthreads();   // previous PV readers of Ks/Vs done (covers Q on kb=0)

        // ---- stage K (perm) and V (plain) ----
#pragma unroll
        for (int p = 0; p < 4; p++) {
            const int idx = p * 1024 + tid * 4;
            const int r = idx >> 6, d0 = idx & 63;
            const float4 kv = *(const float4*)(Kb + (kr + r) * D_MODEL + c0 + d0);
            unsigned* kd = Ks + r * ASTR;
            kd[kperm(d0 + 0)] = f2tf(kv.x);
            kd[kperm(d0 + 1)] = f2tf(kv.y);
            kd[kperm(d0 + 2)] = f2tf(kv.z);
            kd[kperm(d0 + 3)] = f2tf(kv.w);
            const float4 vv = *(const float4*)(Vb + (kr + r) * D_MODEL + c0 + d0);
            uint4 vt;
            vt.x = f2tf(vv.x); vt.y = f2tf(vv.y); vt.z = f2tf(vv.z); vt.w = f2tf(vv.w);
            *(uint4*)(Vs + r * ASTR + d0) = vt;
        }
        __syncthreads();

        // ---- S = Q K^T (per warp: 32 q-rows x 64 keys) ----
        float sa[2][8][4];
#pragma unroll
        for (int ma = 0; ma < 2; ma++)
#pragma unroll
            for (int na = 0; na < 8; na++)
#pragma unroll
                for (int r = 0; r < 4; r++) sa[ma][na][r] = 0.0f;

#pragma unroll
        for (int s = 0; s < 8; s++) {
            unsigned aq[2][4];
#pragma unroll
            for (int ma = 0; ma < 2; ma++) {
                const uint2 t0 = *(const uint2*)(Qs + (wq + ma * 16 + g)     * ASTR + s * 8 + 2 * c);
                const uint2 t1 = *(const uint2*)(Qs + (wq + ma * 16 + g + 8) * ASTR + s * 8 + 2 * c);
                aq[ma][0] = t0.x; aq[ma][1] = t1.x; aq[ma][2] = t0.y; aq[ma][3] = t1.y;
            }
#pragma unroll
            for (int na = 0; na < 8; na++) {
                const uint2 t = *(const uint2*)(Ks + (na * 8 + g) * ASTR + s * 8 + 2 * c);
                unsigned bk[2] = {t.x, t.y};
#pragma unroll
                for (int ma = 0; ma < 2; ma++) mma8(sa[ma][na], aq[ma], bk);
            }
        }

        // ---- online softmax (exp2 domain) + stage P (tf32, perm) ----
#pragma unroll
        for (int ma = 0; ma < 2; ma++) {
#pragma unroll
            for (int hf = 0; hf < 2; hf++) {
                float mx = -1e30f;
#pragma unroll
                for (int na = 0; na < 8; na++)
                    mx = fmaxf(mx, fmaxf(sa[ma][na][2 * hf], sa[ma][na][2 * hf + 1]));
                mx = fmaxf(mx, __shfl_xor_sync(0xffffffffu, mx, 1));
                mx = fmaxf(mx, __shfl_xor_sync(0xffffffffu, mx, 2));
                const float mnew  = fmaxf(mrun[ma][hf], mx);
                const float alpha = exp2f(mrun[ma][hf] - mnew);
                mrun[ma][hf] = mnew;

                float rs = 0.0f;
                unsigned* prow = Ps + (wq + ma * 16 + hf * 8 + g) * ASTR;
#pragma unroll
                for (int na = 0; na < 8; na++) {
                    const float p0 = exp2f(sa[ma][na][2 * hf]     - mnew);
                    const float p1 = exp2f(sa[ma][na][2 * hf + 1] - mnew);
                    rs += p0 + p1;
                    prow[na * 8 + pe] = f2tf(p0);
                    prow[na * 8 + po] = f2tf(p1);
                    o[ma][na][2 * hf]     *= alpha;
                    o[ma][na][2 * hf + 1] *= alpha;
                }
                rs += __shfl_xor_sync(0xffffffffu, rs, 1);
                rs += __shfl_xor_sync(0xffffffffu, rs, 2);
                lrun[ma][hf] = lrun[ma][hf] * alpha + rs;
            }
        }
        __syncwarp();   // P rows are warp-local: cross-lane visibility only

        // ---- O += P V (contraction over 64 keys) ----
#pragma unroll
        for (int s = 0; s < 8; s++) {
            unsigned ap[2][4];
#pragma unroll
            for (int ma = 0; ma < 2; ma++) {
                const uint2 t0 = *(const uint2*)(Ps + (wq + ma * 16 + g)     * ASTR + s * 8 + 2 * c);
                const uint2 t1 = *(const uint2*)(Ps + (wq + ma * 16 + g + 8) * ASTR + s * 8 + 2 * c);
                ap[ma][0] = t0.x; ap[ma][1] = t1.x; ap[ma][2] = t0.y; ap[ma][3] = t1.y;
            }
#pragma unroll
            for (int na = 0; na < 8; na++) {
                unsigned bv[2];
                bv[0] = Vs[(s * 8 + c)     * ASTR + na * 8 + g];
                bv[1] = Vs[(s * 8 + c + 4) * ASTR + na * 8 + g];
#pragma unroll
                for (int ma = 0; ma < 2; ma++) mma8(o[ma][na], ap[ma], bv);
            }
        }
    }

    // ---- epilogue: O /= l, write concat-head layout [S, D_MODEL] ----
#pragma unroll
    for (int ma = 0; ma < 2; ma++)
#pragma unroll
        for (int hf = 0; hf < 2; hf++) {
            const float inv = 1.0f / lrun[ma][hf];
            const int row = q0 + wq + ma * 16 + hf * 8 + g;
#pragma unroll
            for (int na = 0; na < 8; na++) {
                float2 w;
                w.x = o[ma][na][2 * hf]     * inv;
                w.y = o[ma][na][2 * hf + 1] * inv;
                *(float2*)(Ob + row * D_MODEL + c0 + na * 8 + 2 * c) = w;
            }
        }
}

// ============================================================================
// Launch
// ============================================================================
extern "C" void kernel_launch(void* const* d_in, const int* in_sizes, int n_in,
                              void* d_out, int out_size) {
    (void)in_sizes; (void)n_in; (void)out_size;
    const float* query = (const float*)d_in[0];
    const float* key   = (const float*)d_in[1];
    const float* value = (const float*)d_in[2];
    const float* Wq = (const float*)d_in[3];
    const float* bq = (const float*)d_in[4];
    const float* Wk = (const float*)d_in[5];
    const float* bk = (const float*)d_in[6];
    const float* Wv = (const float*)d_in[7];
    const float* bv = (const float*)d_in[8];
    const float* Wo = (const float*)d_in[9];
    const float* bo = (const float*)d_in[10];
    float* out = (float*)d_out;

    float *pQ, *pK, *pV, *pO;
    cudaGetSymbolAddress((void**)&pQ, g_Q);
    cudaGetSymbolAddress((void**)&pK, g_K);
    cudaGetSymbolAddress((void**)&pV, g_V);
    cudaGetSymbolAddress((void**)&pO, g_O);

    const int ASMEM = (2 * MQ + 2 * 64) * ASTR * (int)sizeof(unsigned);  // 184320 B
    cudaFuncSetAttribute(attn_tf32, cudaFuncAttributeMaxDynamicSharedMemorySize, ASMEM);

    dim3 gg(D_MODEL / 128, SEQ / 128);   // (8, 32)
    gemm_tf32<<<gg, 256>>>(query, Wq, bq, pQ);
    gemm_tf32<<<gg, 256>>>(key,   Wk, bk, pK);
    gemm_tf32<<<gg, 256>>>(value, Wv, bv, pV);

    dim3 ga(SEQ / MQ, NHEAD);            // (16, 16)
    attn_tf32<<<ga, 256, ASMEM>>>(pQ, pK, pV, pO);

    gemm_tf32<<<gg, 256>>>(pO, Wo, bo, out);
}

// round 10
// speedup vs baseline: 2.1922x; 1.0005x over previous
#include <cuda_runtime.h>
#include <math.h>

#define D_MODEL 1024
#define SEQ     4096
#define NHEAD   16
#define DK      64

// Scratch (allocation-free: __device__ globals)
__device__ float g_Q[SEQ * D_MODEL];
__device__ float g_K[SEQ * D_MODEL];
__device__ float g_V[SEQ * D_MODEL];
__device__ float g_O[SEQ * D_MODEL];

// ---------------------------------------------------------------------------
// tf32 helpers. cvt.rna (round-to-nearest) is REQUIRED: raw-bit truncation in
// the mma gives a correlated -2^-11 bias per operand -> ~1e-3 systematic error.
// ---------------------------------------------------------------------------
__device__ __forceinline__ unsigned f2tf(float x) {
    unsigned y;
    asm("cvt.rna.tf32.f32 %0, %1;" : "=r"(y) : "f"(x));
    return y;
}

// D += A(16x8) * B(8x8), tf32 in, fp32 accum
__device__ __forceinline__ void mma8(float* d, const unsigned* a, const unsigned* b) {
    asm volatile(
        "mma.sync.aligned.m16n8k8.row.col.f32.tf32.tf32.f32 "
        "{%0,%1,%2,%3}, {%4,%5,%6,%7}, {%8,%9}, {%0,%1,%2,%3};\n"
        : "+f"(d[0]), "+f"(d[1]), "+f"(d[2]), "+f"(d[3])
        : "r"(a[0]), "r"(a[1]), "r"(a[2]), "r"(a[3]), "r"(b[0]), "r"(b[1]));
}

// Permutation within each 8-wide k-block so that the (c, c+4) fragment pair is
// adjacent in smem -> every fragment load is one LDS.64.
// pos(k) = (k & ~7) + (k%4)*2 + (k/4)%2
__device__ __forceinline__ int kperm(int k) {
    return (k & ~7) + ((k & 3) << 1) + ((k >> 2) & 1);
}

// ============================================================================
// GEMM: C[M,1024] = A[M,1024] @ W[1024,1024]^T + bias  (tf32 mma, NT)
// Tile 128x128x16, 8 warps as 2(M)x4(N), warp tile 64x32 (4 m-atoms x 4 n-atoms).
// smem stride 24 words: fragment LDS.64 banks = {24g%32 + 2c + w} -> conflict-free.
// ============================================================================
#define GSTR 24

__global__ __launch_bounds__(256, 2)
void gemm_tf32(const float* __restrict__ A, const float* __restrict__ W,
               const float* __restrict__ bias, float* __restrict__ C) {
    __shared__ unsigned As[128 * GSTR];
    __shared__ unsigned Bs[128 * GSTR];

    const int tid  = threadIdx.x;
    const int lane = tid & 31;
    const int warp = tid >> 5;
    const int g = lane >> 2, c = lane & 3;
    const int wm = (warp >> 2) * 64;      // 0 / 64
    const int wn = (warp & 3) * 32;       // 0,32,64,96
    const int bm = blockIdx.y * 128;
    const int bn = blockIdx.x * 128;

    const int srow = tid >> 1;            // 0..127
    const int sk   = (tid & 1) * 8;       // 0 / 8
    const float* Ap = A + (bm + srow) * D_MODEL + sk;
    const float* Wp = W + (bn + srow) * D_MODEL + sk;

    float acc[4][4][4];
#pragma unroll
    for (int i = 0; i < 4; i++)
#pragma unroll
        for (int j = 0; j < 4; j++)
#pragma unroll
            for (int r = 0; r < 4; r++) acc[i][j][r] = 0.0f;

    // register prefetch of first slab
    float4 av0 = *(const float4*)Ap;
    float4 av1 = *(const float4*)(Ap + 4);
    float4 wv0 = *(const float4*)Wp;
    float4 wv1 = *(const float4*)(Wp + 4);

    for (int k0 = 0; k0 < D_MODEL; k0 += 16) {
        __syncthreads();
        {
            unsigned* ad = As + srow * GSTR + sk;
            unsigned* bd = Bs + srow * GSTR + sk;
            const float aj[8] = {av0.x, av0.y, av0.z, av0.w, av1.x, av1.y, av1.z, av1.w};
            const float wj[8] = {wv0.x, wv0.y, wv0.z, wv0.w, wv1.x, wv1.y, wv1.z, wv1.w};
#pragma unroll
            for (int j = 0; j < 8; j++) {
                const int p = ((j & 3) << 1) + (j >> 2);
                ad[p] = f2tf(aj[j]);
                bd[p] = f2tf(wj[j]);
            }
        }
        __syncthreads();

        if (k0 + 16 < D_MODEL) {          // prefetch next slab under compute
            av0 = *(const float4*)(Ap + k0 + 16);
            av1 = *(const float4*)(Ap + k0 + 20);
            wv0 = *(const float4*)(Wp + k0 + 16);
            wv1 = *(const float4*)(Wp + k0 + 20);
        }

#pragma unroll
        for (int s = 0; s < 2; s++) {     // two k8 steps per slab
            unsigned af[4][4], bf[4][2];
#pragma unroll
            for (int ma = 0; ma < 4; ma++) {
                const uint2 t0 = *(const uint2*)(As + (wm + ma * 16 + g)     * GSTR + s * 8 + c * 2);
                const uint2 t1 = *(const uint2*)(As + (wm + ma * 16 + g + 8) * GSTR + s * 8 + c * 2);
                af[ma][0] = t0.x; af[ma][1] = t1.x; af[ma][2] = t0.y; af[ma][3] = t1.y;
            }
#pragma unroll
            for (int na = 0; na < 4; na++) {
                const uint2 t = *(const uint2*)(Bs + (wn + na * 8 + g) * GSTR + s * 8 + c * 2);
                bf[na][0] = t.x; bf[na][1] = t.y;
            }
#pragma unroll
            for (int ma = 0; ma < 4; ma++)
#pragma unroll
                for (int na = 0; na < 4; na++)
                    mma8(acc[ma][na], af[ma], bf[na]);
        }
    }

    // epilogue: + bias, float2 stores (C layout: row g/g+8, cols 2c,2c+1)
#pragma unroll
    for (int na = 0; na < 4; na++) {
        const int col = bn + wn + na * 8 + 2 * c;
        const float2 bb = *(const float2*)(bias + col);
#pragma unroll
        for (int ma = 0; ma < 4; ma++) {
            const int r0 = bm + wm + ma * 16 + g;
            float2 v0 = {acc[ma][na][0] + bb.x, acc[ma][na][1] + bb.y};
            float2 v1 = {acc[ma][na][2] + bb.x, acc[ma][na][3] + bb.y};
            *(float2*)(C + r0 * D_MODEL + col)       = v0;
            *(float2*)(C + (r0 + 8) * D_MODEL + col) = v1;
        }
    }
}

// ============================================================================
// Flash attention with tf32 mma. One CTA = (head, 256-query block).
// 8 warps, each owns 32 query rows (2 m-atoms) -> softmax is warp-local
// (row reduction = shfl over the lane%4 quad). K/V blocks of 64 keys.
// Qs/Ks/Ps use the kperm layout (LDS.64 fragments, stride 72 conflict-free);
// Vs stored plain: PV B-fragments are scalar LDS with banks 8c+g = 0..31.
// exp via exp2f with log2(e)/8 folded into Q.
// ============================================================================
#define ASTR 72
#define MQ   256

__global__ __launch_bounds__(256, 1)
void attn_tf32(const float* __restrict__ Qb, const float* __restrict__ Kb,
               const float* __restrict__ Vb, float* __restrict__ Ob) {
    extern __shared__ unsigned smA[];
    unsigned* Qs = smA;                 // [MQ][ASTR]  perm(d)
    unsigned* Ps = Qs + MQ * ASTR;      // [MQ][ASTR]  perm(key)
    unsigned* Ks = Ps + MQ * ASTR;      // [64][ASTR]  perm(d)
    unsigned* Vs = Ks + 64 * ASTR;      // [64][ASTR]  plain d

    const int tid = threadIdx.x, lane = tid & 31, warp = tid >> 5;
    const int g = lane >> 2, c = lane & 3;
    const int h = blockIdx.y, q0 = blockIdx.x * MQ, c0 = h * DK;
    const int wq = warp * 32;

    const float QS = 0.125f * 1.4426950408889634f;   // (1/sqrt(dk)) * log2(e)

    // ---- stage Q (scaled, tf32, perm) ----
#pragma unroll
    for (int p = 0; p < (MQ * DK) / (256 * 4); p++) {   // 16 passes
        const int idx = p * 1024 + tid * 4;
        const int r = idx >> 6, d0 = idx & 63;
        const float4 v = *(const float4*)(Qb + (q0 + r) * D_MODEL + c0 + d0);
        unsigned* dst = Qs + r * ASTR;
        const float vv[4] = {v.x, v.y, v.z, v.w};
#pragma unroll
        for (int j = 0; j < 4; j++) dst[kperm(d0 + j)] = f2tf(vv[j] * QS);
    }

    float o[2][8][4];
    float mrun[2][2], lrun[2][2];
#pragma unroll
    for (int ma = 0; ma < 2; ma++) {
        mrun[ma][0] = mrun[ma][1] = -1e30f;
        lrun[ma][0] = lrun[ma][1] = 0.0f;
#pragma unroll
        for (int na = 0; na < 8; na++)
#pragma unroll
            for (int r = 0; r < 4; r++) o[ma][na][r] = 0.0f;
    }

    const int pe = ((2 * c) & 3) * 2 + (((2 * c) >> 2) & 1);          // {0,4,1,5}
    const int po = ((2 * c + 1) & 3) * 2 + (((2 * c + 1) >> 2) & 1);  // {2,6,3,7}

    for (int kb = 0; kb < SEQ / 64; kb++) {
        const int kr = kb * 64;
        __syncthreads();   // previous PV readers of Ks/Vs done (covers Q on kb=0)

        // ---- stage K (perm) and V (plain) ----
#pragma unroll
        for (int p = 0; p < 4; p++) {
            const int idx = p * 1024 + tid * 4;
            const int r = idx >> 6, d0 = idx & 63;
            const float4 kv = *(const float4*)(Kb + (kr + r) * D_MODEL + c0 + d0);
            unsigned* kd = Ks + r * ASTR;
            kd[kperm(d0 + 0)] = f2tf(kv.x);
            kd[kperm(d0 + 1)] = f2tf(kv.y);
            kd[kperm(d0 + 2)] = f2tf(kv.z);
            kd[kperm(d0 + 3)] = f2tf(kv.w);
            const float4 vv = *(const float4*)(Vb + (kr + r) * D_MODEL + c0 + d0);
            uint4 vt;
            vt.x = f2tf(vv.x); vt.y = f2tf(vv.y); vt.z = f2tf(vv.z); vt.w = f2tf(vv.w);
            *(uint4*)(Vs + r * ASTR + d0) = vt;
        }
        __syncthreads();

        // ---- S = Q K^T (per warp: 32 q-rows x 64 keys) ----
        float sa[2][8][4];
#pragma unroll
        for (int ma = 0; ma < 2; ma++)
#pragma unroll
            for (int na = 0; na < 8; na++)
#pragma unroll
                for (int r = 0; r < 4; r++) sa[ma][na][r] = 0.0f;

#pragma unroll
        for (int s = 0; s < 8; s++) {
            unsigned aq[2][4];
#pragma unroll
            for (int ma = 0; ma < 2; ma++) {
                const uint2 t0 = *(const uint2*)(Qs + (wq + ma * 16 + g)     * ASTR + s * 8 + 2 * c);
                const uint2 t1 = *(const uint2*)(Qs + (wq + ma * 16 + g + 8) * ASTR + s * 8 + 2 * c);
                aq[ma][0] = t0.x; aq[ma][1] = t1.x; aq[ma][2] = t0.y; aq[ma][3] = t1.y;
            }
#pragma unroll
            for (int na = 0; na < 8; na++) {
                const uint2 t = *(const uint2*)(Ks + (na * 8 + g) * ASTR + s * 8 + 2 * c);
                unsigned bk[2] = {t.x, t.y};
#pragma unroll
                for (int ma = 0; ma < 2; ma++) mma8(sa[ma][na], aq[ma], bk);
            }
        }

        // ---- online softmax (exp2 domain) + stage P (tf32, perm) ----
#pragma unroll
        for (int ma = 0; ma < 2; ma++) {
#pragma unroll
            for (int hf = 0; hf < 2; hf++) {
                float mx = -1e30f;
#pragma unroll
                for (int na = 0; na < 8; na++)
                    mx = fmaxf(mx, fmaxf(sa[ma][na][2 * hf], sa[ma][na][2 * hf + 1]));
                mx = fmaxf(mx, __shfl_xor_sync(0xffffffffu, mx, 1));
                mx = fmaxf(mx, __shfl_xor_sync(0xffffffffu, mx, 2));
                const float mnew  = fmaxf(mrun[ma][hf], mx);
                const float alpha = exp2f(mrun[ma][hf] - mnew);
                mrun[ma][hf] = mnew;

                float rs = 0.0f;
                unsigned* prow = Ps + (wq + ma * 16 + hf * 8 + g) * ASTR;
#pragma unroll
                for (int na = 0; na < 8; na++) {
                    const float p0 = exp2f(sa[ma][na][2 * hf]     - mnew);
                    const float p1 = exp2f(sa[ma][na][2 * hf + 1] - mnew);
                    rs += p0 + p1;
                    prow[na * 8 + pe] = f2tf(p0);
                    prow[na * 8 + po] = f2tf(p1);
                    o[ma][na][2 * hf]     *= alpha;
                    o[ma][na][2 * hf + 1] *= alpha;
                }
                rs += __shfl_xor_sync(0xffffffffu, rs, 1);
                rs += __shfl_xor_sync(0xffffffffu, rs, 2);
                lrun[ma][hf] = lrun[ma][hf] * alpha + rs;
            }
        }
        __syncwarp();   // P rows are warp-local: cross-lane visibility only

        // ---- O += P V (contraction over 64 keys) ----
#pragma unroll
        for (int s = 0; s < 8; s++) {
            unsigned ap[2][4];
#pragma unroll
            for (int ma = 0; ma < 2; ma++) {
                const uint2 t0 = *(const uint2*)(Ps + (wq + ma * 16 + g)     * ASTR + s * 8 + 2 * c);
                const uint2 t1 = *(const uint2*)(Ps + (wq + ma * 16 + g + 8) * ASTR + s * 8 + 2 * c);
                ap[ma][0] = t0.x; ap[ma][1] = t1.x; ap[ma][2] = t0.y; ap[ma][3] = t1.y;
            }
#pragma unroll
            for (int na = 0; na < 8; na++) {
                unsigned bv[2];
                bv[0] = Vs[(s * 8 + c)     * ASTR + na * 8 + g];
                bv[1] = Vs[(s * 8 + c + 4) * ASTR + na * 8 + g];
#pragma unroll
                for (int ma = 0; ma < 2; ma++) mma8(o[ma][na], ap[ma], bv);
            }
        }
    }

    // ---- epilogue: O /= l, write concat-head layout [S, D_MODEL] ----
#pragma unroll
    for (int ma = 0; ma < 2; ma++)
#pragma unroll
        for (int hf = 0; hf < 2; hf++) {
            const float inv = 1.0f / lrun[ma][hf];
            const int row = q0 + wq + ma * 16 + hf * 8 + g;
#pragma unroll
            for (int na = 0; na < 8; na++) {
                float2 w;
                w.x = o[ma][na][2 * hf]     * inv;
                w.y = o[ma][na][2 * hf + 1] * inv;
                *(float2*)(Ob + row * D_MODEL + c0 + na * 8 + 2 * c) = w;
            }
        }
}

// ============================================================================
// Launch
// ============================================================================
extern "C" void kernel_launch(void* const* d_in, const int* in_sizes, int n_in,
                              void* d_out, int out_size) {
    (void)in_sizes; (void)n_in; (void)out_size;
    const float* query = (const float*)d_in[0];
    const float* key   = (const float*)d_in[1];
    const float* value = (const float*)d_in[2];
    const float* Wq = (const float*)d_in[3];
    const float* bq = (const float*)d_in[4];
    const float* Wk = (const float*)d_in[5];
    const float* bk = (const float*)d_in[6];
    const float* Wv = (const float*)d_in[7];
    const float* bv = (const float*)d_in[8];
    const float* Wo = (const float*)d_in[9];
    const float* bo = (const float*)d_in[10];
    float* out = (float*)d_out;

    float *pQ, *pK, *pV, *pO;
    cudaGetSymbolAddress((void**)&pQ, g_Q);
    cudaGetSymbolAddress((void**)&pK, g_K);
    cudaGetSymbolAddress((void**)&pV, g_V);
    cudaGetSymbolAddress((void**)&pO, g_O);

    const int ASMEM = (2 * MQ + 2 * 64) * ASTR * (int)sizeof(unsigned);  // 184320 B
    cudaFuncSetAttribute(attn_tf32, cudaFuncAttributeMaxDynamicSharedMemorySize, ASMEM);

    dim3 gg(D_MODEL / 128, SEQ / 128);   // (8, 32)
    gemm_tf32<<<gg, 256>>>(query, Wq, bq, pQ);
    gemm_tf32<<<gg, 256>>>(key,   Wk, bk, pK);
    gemm_tf32<<<gg, 256>>>(value, Wv, bv, pV);

    dim3 ga(SEQ / MQ, NHEAD);            // (16, 16)
    attn_tf32<<<ga, 256, ASMEM>>>(pQ, pK, pV, pO);

    gemm_tf32<<<gg, 256>>>(pO, Wo, bo, out);
}

// round 11
// speedup vs baseline: 2.7273x; 1.2441x over previous
#include <cuda_runtime.h>
#include <math.h>

#define D_MODEL 1024
#define SEQ     4096
#define NHEAD   16
#define DK      64

// Scratch (allocation-free: __device__ globals)
__device__ float g_Q[SEQ * D_MODEL];
__device__ float g_K[SEQ * D_MODEL];
__device__ float g_V[SEQ * D_MODEL];
__device__ float g_O[SEQ * D_MODEL];

// ---------------------------------------------------------------------------
// tf32 helpers. cvt.rna (round-to-nearest) is REQUIRED: raw-bit truncation in
// the mma gives a correlated -2^-11 bias per operand -> ~1e-3 systematic error.
// ---------------------------------------------------------------------------
__device__ __forceinline__ unsigned f2tf(float x) {
    unsigned y;
    asm("cvt.rna.tf32.f32 %0, %1;" : "=r"(y) : "f"(x));
    return y;
}

// D += A(16x8) * B(8x8), tf32 in, fp32 accum
__device__ __forceinline__ void mma8(float* d, const unsigned* a, const unsigned* b) {
    asm volatile(
        "mma.sync.aligned.m16n8k8.row.col.f32.tf32.tf32.f32 "
        "{%0,%1,%2,%3}, {%4,%5,%6,%7}, {%8,%9}, {%0,%1,%2,%3};\n"
        : "+f"(d[0]), "+f"(d[1]), "+f"(d[2]), "+f"(d[3])
        : "r"(a[0]), "r"(a[1]), "r"(a[2]), "r"(a[3]), "r"(b[0]), "r"(b[1]));
}

// Permutation within each 8-wide k-block so that the (c, c+4) fragment pair is
// adjacent in smem -> every fragment load is one LDS.64.
__device__ __forceinline__ int kperm(int k) {
    return (k & ~7) + ((k & 3) << 1) + ((k >> 2) & 1);
}

// ============================================================================
// GEMM core: C[M,1024] = A[M,1024] @ W[1024,1024]^T + bias  (tf32 mma, NT)
// Tile 128x128x16, 8 warps as 2(M)x4(N), warp tile 64x32.
// DOUBLE-BUFFERED smem: one __syncthreads per 16-k slab; next slab's LDG is
// issued before compute and stored to the alternate buffer after compute.
// ============================================================================
#define GSTR 24
#define GBUF (128 * GSTR)

__device__ __forceinline__ void gemm_store_slab(unsigned* ad, unsigned* bd,
                                                float4 av0, float4 av1,
                                                float4 wv0, float4 wv1) {
    const float aj[8] = {av0.x, av0.y, av0.z, av0.w, av1.x, av1.y, av1.z, av1.w};
    const float wj[8] = {wv0.x, wv0.y, wv0.z, wv0.w, wv1.x, wv1.y, wv1.z, wv1.w};
#pragma unroll
    for (int j = 0; j < 8; j++) {
        const int p = ((j & 3) << 1) + (j >> 2);
        ad[p] = f2tf(aj[j]);
        bd[p] = f2tf(wj[j]);
    }
}

__device__ __forceinline__ void gemm_core(const float* __restrict__ A,
                                          const float* __restrict__ W,
                                          const float* __restrict__ bias,
                                          float* __restrict__ C,
                                          int bx, int by) {
    extern __shared__ unsigned gsm[];
    unsigned* As = gsm;              // [2][128*GSTR]
    unsigned* Bs = gsm + 2 * GBUF;   // [2][128*GSTR]

    const int tid  = threadIdx.x;
    const int lane = tid & 31;
    const int warp = tid >> 5;
    const int g = lane >> 2, c = lane & 3;
    const int wm = (warp >> 2) * 64;
    const int wn = (warp & 3) * 32;
    const int bm = by * 128;
    const int bn = bx * 128;

    const int srow = tid >> 1;
    const int sk   = (tid & 1) * 8;
    const float* Ap = A + (bm + srow) * D_MODEL + sk;
    const float* Wp = W + (bn + srow) * D_MODEL + sk;
    unsigned* adst = As + srow * GSTR + sk;
    unsigned* bdst = Bs + srow * GSTR + sk;

    float acc[4][4][4];
#pragma unroll
    for (int i = 0; i < 4; i++)
#pragma unroll
        for (int j = 0; j < 4; j++)
#pragma unroll
            for (int r = 0; r < 4; r++) acc[i][j][r] = 0.0f;

    // prologue: stage slab 0 into buffer 0
    {
        float4 av0 = *(const float4*)Ap;
        float4 av1 = *(const float4*)(Ap + 4);
        float4 wv0 = *(const float4*)Wp;
        float4 wv1 = *(const float4*)(Wp + 4);
        gemm_store_slab(adst, bdst, av0, av1, wv0, wv1);
    }
    __syncthreads();

    for (int k0 = 0; k0 < D_MODEL; k0 += 16) {
        const int buf = (k0 >> 4) & 1;
        const unsigned* Acur = As + buf * GBUF;
        const unsigned* Bcur = Bs + buf * GBUF;
        const bool more = (k0 + 16) < D_MODEL;

        // issue next slab's global loads first (latency overlaps compute)
        float4 av0, av1, wv0, wv1;
        if (more) {
            av0 = *(const float4*)(Ap + k0 + 16);
            av1 = *(const float4*)(Ap + k0 + 20);
            wv0 = *(const float4*)(Wp + k0 + 16);
            wv1 = *(const float4*)(Wp + k0 + 20);
        }

#pragma unroll
        for (int s = 0; s < 2; s++) {
            unsigned af[4][4], bf[4][2];
#pragma unroll
            for (int ma = 0; ma < 4; ma++) {
                const uint2 t0 = *(const uint2*)(Acur + (wm + ma * 16 + g)     * GSTR + s * 8 + c * 2);
                const uint2 t1 = *(const uint2*)(Acur + (wm + ma * 16 + g + 8) * GSTR + s * 8 + c * 2);
                af[ma][0] = t0.x; af[ma][1] = t1.x; af[ma][2] = t0.y; af[ma][3] = t1.y;
            }
#pragma unroll
            for (int na = 0; na < 4; na++) {
                const uint2 t = *(const uint2*)(Bcur + (wn + na * 8 + g) * GSTR + s * 8 + c * 2);
                bf[na][0] = t.x; bf[na][1] = t.y;
            }
#pragma unroll
            for (int ma = 0; ma < 4; ma++)
#pragma unroll
                for (int na = 0; na < 4; na++)
                    mma8(acc[ma][na], af[ma], bf[na]);
        }

        if (more)
            gemm_store_slab(adst + (buf ^ 1) * GBUF, bdst + (buf ^ 1) * GBUF,
                            av0, av1, wv0, wv1);
        __syncthreads();
    }

    // epilogue: + bias, float2 stores
#pragma unroll
    for (int na = 0; na < 4; na++) {
        const int col = bn + wn + na * 8 + 2 * c;
        const float2 bb = *(const float2*)(bias + col);
#pragma unroll
        for (int ma = 0; ma < 4; ma++) {
            const int r0 = bm + wm + ma * 16 + g;
            float2 v0 = {acc[ma][na][0] + bb.x, acc[ma][na][1] + bb.y};
            float2 v1 = {acc[ma][na][2] + bb.x, acc[ma][na][3] + bb.y};
            *(float2*)(C + r0 * D_MODEL + col)       = v0;
            *(float2*)(C + (r0 + 8) * D_MODEL + col) = v1;
        }
    }
}

// Fused Q/K/V projection: blockIdx.z selects {query,key,value} x {Wq,Wk,Wv}.
__global__ __launch_bounds__(256, 2)
void gemm_qkv(const float* __restrict__ xq, const float* __restrict__ xk,
              const float* __restrict__ xv,
              const float* __restrict__ Wq, const float* __restrict__ bq,
              const float* __restrict__ Wk, const float* __restrict__ bk,
              const float* __restrict__ Wv, const float* __restrict__ bv,
              float* __restrict__ Cq, float* __restrict__ Ck, float* __restrict__ Cv) {
    const float *A, *W, *b;
    float* C;
    if (blockIdx.z == 0)      { A = xq; W = Wq; b = bq; C = Cq; }
    else if (blockIdx.z == 1) { A = xk; W = Wk; b = bk; C = Ck; }
    else                      { A = xv; W = Wv; b = bv; C = Cv; }
    gemm_core(A, W, b, C, blockIdx.x, blockIdx.y);
}

__global__ __launch_bounds__(256, 2)
void gemm_one(const float* __restrict__ A, const float* __restrict__ W,
              const float* __restrict__ bias, float* __restrict__ C) {
    gemm_core(A, W, bias, C, blockIdx.x, blockIdx.y);
}

// ============================================================================
// Flash attention, tf32 mma. One CTA = (head, 128-query block), 2 CTAs/SM.
// 8 warps, each owns 16 query rows -> softmax warp-local. 64-key blocks.
// Qs/Ks/Ps in kperm layout (stride 72, conflict-free LDS.64 fragments);
// Vs plain (PV B-frags are scalar LDS with banks 8c+g covering 0..31).
// ============================================================================
#define ASTR 72
#define MQ   128

__global__ __launch_bounds__(256, 2)
void attn_tf32(const float* __restrict__ Qb, const float* __restrict__ Kb,
               const float* __restrict__ Vb, float* __restrict__ Ob) {
    extern __shared__ unsigned smA[];
    unsigned* Qs = smA;                 // [MQ][ASTR]  perm(d)
    unsigned* Ps = Qs + MQ * ASTR;      // [MQ][ASTR]  perm(key)
    unsigned* Ks = Ps + MQ * ASTR;      // [64][ASTR]  perm(d)
    unsigned* Vs = Ks + 64 * ASTR;      // [64][ASTR]  plain d

    const int tid = threadIdx.x, lane = tid & 31, warp = tid >> 5;
    const int g = lane >> 2, c = lane & 3;
    const int h = blockIdx.y, q0 = blockIdx.x * MQ, c0 = h * DK;
    const int wq = warp * 16;

    const float QS = 0.125f * 1.4426950408889634f;   // (1/sqrt(dk)) * log2(e)

    // ---- stage Q (scaled, tf32, perm) : 8 passes ----
#pragma unroll
    for (int p = 0; p < (MQ * DK) / (256 * 4); p++) {
        const int idx = p * 1024 + tid * 4;
        const int r = idx >> 6, d0 = idx & 63;
        const float4 v = *(const float4*)(Qb + (q0 + r) * D_MODEL + c0 + d0);
        unsigned* dst = Qs + r * ASTR;
        const float vv[4] = {v.x, v.y, v.z, v.w};
#pragma unroll
        for (int j = 0; j < 4; j++) dst[kperm(d0 + j)] = f2tf(vv[j] * QS);
    }

    float o[8][4];
    float mrun[2], lrun[2];
    mrun[0] = mrun[1] = -1e30f;
    lrun[0] = lrun[1] = 0.0f;
#pragma unroll
    for (int na = 0; na < 8; na++)
#pragma unroll
        for (int r = 0; r < 4; r++) o[na][r] = 0.0f;

    const int pe = ((2 * c) & 3) * 2 + (((2 * c) >> 2) & 1);          // {0,4,1,5}
    const int po = ((2 * c + 1) & 3) * 2 + (((2 * c + 1) >> 2) & 1);  // {2,6,3,7}

    for (int kb = 0; kb < SEQ / 64; kb++) {
        const int kr = kb * 64;
        __syncthreads();   // previous PV readers of Ks/Vs done (covers Qs on kb=0)

        // ---- stage K (perm) and V (plain) : 4 passes ----
#pragma unroll
        for (int p = 0; p < 4; p++) {
            const int idx = p * 1024 + tid * 4;
            const int r = idx >> 6, d0 = idx & 63;
            const float4 kv = *(const float4*)(Kb + (kr + r) * D_MODEL + c0 + d0);
            unsigned* kd = Ks + r * ASTR;
            kd[kperm(d0 + 0)] = f2tf(kv.x);
            kd[kperm(d0 + 1)] = f2tf(kv.y);
            kd[kperm(d0 + 2)] = f2tf(kv.z);
            kd[kperm(d0 + 3)] = f2tf(kv.w);
            const float4 vv = *(const float4*)(Vb + (kr + r) * D_MODEL + c0 + d0);
            uint4 vt;
            vt.x = f2tf(vv.x); vt.y = f2tf(vv.y); vt.z = f2tf(vv.z); vt.w = f2tf(vv.w);
            *(uint4*)(Vs + r * ASTR + d0) = vt;
        }
        __syncthreads();

        // ---- S = Q K^T (per warp: 16 q-rows x 64 keys) ----
        float sa[8][4];
#pragma unroll
        for (int na = 0; na < 8; na++)
#pragma unroll
            for (int r = 0; r < 4; r++) sa[na][r] = 0.0f;

#pragma unroll
        for (int s = 0; s < 8; s++) {
            unsigned aq[4];
            {
                const uint2 t0 = *(const uint2*)(Qs + (wq + g)     * ASTR + s * 8 + 2 * c);
                const uint2 t1 = *(const uint2*)(Qs + (wq + g + 8) * ASTR + s * 8 + 2 * c);
                aq[0] = t0.x; aq[1] = t1.x; aq[2] = t0.y; aq[3] = t1.y;
            }
#pragma unroll
            for (int na = 0; na < 8; na++) {
                const uint2 t = *(const uint2*)(Ks + (na * 8 + g) * ASTR + s * 8 + 2 * c);
                unsigned bk[2] = {t.x, t.y};
                mma8(sa[na], aq, bk);
            }
        }

        // ---- online softmax (exp2 domain) + stage P (tf32, perm) ----
#pragma unroll
        for (int hf = 0; hf < 2; hf++) {
            float mx = -1e30f;
#pragma unroll
            for (int na = 0; na < 8; na++)
                mx = fmaxf(mx, fmaxf(sa[na][2 * hf], sa[na][2 * hf + 1]));
            mx = fmaxf(mx, __shfl_xor_sync(0xffffffffu, mx, 1));
            mx = fmaxf(mx, __shfl_xor_sync(0xffffffffu, mx, 2));
            const float mnew  = fmaxf(mrun[hf], mx);
            const float alpha = exp2f(mrun[hf] - mnew);
            mrun[hf] = mnew;

            float rs = 0.0f;
            unsigned* prow = Ps + (wq + hf * 8 + g) * ASTR;
#pragma unroll
            for (int na = 0; na < 8; na++) {
                const float p0 = exp2f(sa[na][2 * hf]     - mnew);
                const float p1 = exp2f(sa[na][2 * hf + 1] - mnew);
                rs += p0 + p1;
                prow[na * 8 + pe] = f2tf(p0);
                prow[na * 8 + po] = f2tf(p1);
                o[na][2 * hf]     *= alpha;
                o[na][2 * hf + 1] *= alpha;
            }
            rs += __shfl_xor_sync(0xffffffffu, rs, 1);
            rs += __shfl_xor_sync(0xffffffffu, rs, 2);
            lrun[hf] = lrun[hf] * alpha + rs;
        }
        __syncwarp();   // P rows are warp-local: cross-lane visibility only

        // ---- O += P V (contraction over 64 keys) ----
#pragma unroll
        for (int s = 0; s < 8; s++) {
            unsigned ap[4];
            {
                const uint2 t0 = *(const uint2*)(Ps + (wq + g)     * ASTR + s * 8 + 2 * c);
                const uint2 t1 = *(const uint2*)(Ps + (wq + g + 8) * ASTR + s * 8 + 2 * c);
                ap[0] = t0.x; ap[1] = t1.x; ap[2] = t0.y; ap[3] = t1.y;
            }
#pragma unroll
            for (int na = 0; na < 8; na++) {
                unsigned bv[2];
                bv[0] = Vs[(s * 8 + c)     * ASTR + na * 8 + g];
                bv[1] = Vs[(s * 8 + c + 4) * ASTR + na * 8 + g];
                mma8(o[na], ap, bv);
            }
        }
    }

    // ---- epilogue: O /= l, write concat-head layout [S, D_MODEL] ----
#pragma unroll
    for (int hf = 0; hf < 2; hf++) {
        const float inv = 1.0f / lrun[hf];
        const int row = q0 + wq + hf * 8 + g;
#pragma unroll
        for (int na = 0; na < 8; na++) {
            float2 w;
            w.x = o[na][2 * hf]     * inv;
            w.y = o[na][2 * hf + 1] * inv;
            *(float2*)(Ob + row * D_MODEL + c0 + na * 8 + 2 * c) = w;
        }
    }
}

// ============================================================================
// Launch
// ============================================================================
extern "C" void kernel_launch(void* const* d_in, const int* in_sizes, int n_in,
                              void* d_out, int out_size) {
    (void)in_sizes; (void)n_in; (void)out_size;
    const float* query = (const float*)d_in[0];
    const float* key   = (const float*)d_in[1];
    const float* value = (const float*)d_in[2];
    const float* Wq = (const float*)d_in[3];
    const float* bq = (const float*)d_in[4];
    const float* Wk = (const float*)d_in[5];
    const float* bk = (const float*)d_in[6];
    const float* Wv = (const float*)d_in[7];
    const float* bv = (const float*)d_in[8];
    const float* Wo = (const float*)d_in[9];
    const float* bo = (const float*)d_in[10];
    float* out = (float*)d_out;

    float *pQ, *pK, *pV, *pO;
    cudaGetSymbolAddress((void**)&pQ, g_Q);
    cudaGetSymbolAddress((void**)&pK, g_K);
    cudaGetSymbolAddress((void**)&pV, g_V);
    cudaGetSymbolAddress((void**)&pO, g_O);

    const int GSMEM = 4 * GBUF * (int)sizeof(unsigned);                  // 49152 B
    const int ASMEM = (2 * MQ + 2 * 64) * ASTR * (int)sizeof(unsigned);  // 110592 B
    cudaFuncSetAttribute(gemm_qkv, cudaFuncAttributeMaxDynamicSharedMemorySize, GSMEM);
    cudaFuncSetAttribute(gemm_one, cudaFuncAttributeMaxDynamicSharedMemorySize, GSMEM);
    cudaFuncSetAttribute(attn_tf32, cudaFuncAttributeMaxDynamicSharedMemorySize, ASMEM);

    dim3 gq(D_MODEL / 128, SEQ / 128, 3);   // (8, 32, 3)
    gemm_qkv<<<gq, 256, GSMEM>>>(query, key, value, Wq, bq, Wk, bk, Wv, bv,
                                 pQ, pK, pV);

    dim3 ga(SEQ / MQ, NHEAD);               // (32, 16)
    attn_tf32<<<ga, 256, ASMEM>>>(pQ, pK, pV, pO);

    dim3 gg(D_MODEL / 128, SEQ / 128);      // (8, 32)
    gemm_one<<<gg, 256, GSMEM>>>(pO, Wo, bo, out);
}